// round 13
// baseline (speedup 1.0000x reference)
#include <cuda_runtime.h>
#include <cuda_bf16.h>
#include <cstdint>

// Fused soft-VQ, tf32 mma.sync, 512 threads (16 warps), transposed operands,
// cp.async 2-stage C ring reading a pre-converted (RNA tf32) codebook.
//   MMA1: S^T[32j x 128r] = C * X^T   (warp grid 2j x 8r)
//   MMA2: O^T[256d x 128r] = C^T * P^T (warp grid 16d)
// out = softmax(-10 * ||x - C||) @ C ; N=32768, K=8192, D=256

#define DD  256
#define BM  128
#define BN  32
#define THREADS 512
#define XS_STRIDE 260   // 65 quads (odd) -> ldmatrix conflict-free
#define CS_STRIDE 260
#define PS_STRIDE 36    // 9 quads (odd)
#define CS_STAGE  (BN * CS_STRIDE)                  // 8320 floats / stage

#define NMAX 32768
#define KMAX 8192

// smem float offsets
#define OFF_XS 0
#define OFF_CS (OFF_XS + BM * XS_STRIDE)            // 33280
#define OFF_PS (OFF_CS + 2 * CS_STAGE)              // 49920
#define OFF_LB (OFF_PS + BM * PS_STRIDE)            // 54528
#define SMEM_FLOATS (OFF_LB + 2 * BM)               // 54784
#define SMEM_BYTES (SMEM_FLOATS * 4)                // 219136

#define LOG2E10 14.4269504088896f   // 10 * log2(e)

__device__ float g_x2[NMAX];
__device__ float g_c2[KMAX];
__device__ float g_cbt[KMAX * DD];   // codebook pre-converted to tf32 bits

// ---------------- helpers ----------------
__device__ __forceinline__ uint32_t cvt_rna_tf32(float v) {
    uint32_t u;
    asm("cvt.rna.tf32.f32 %0, %1;" : "=r"(u) : "f"(v));
    return u;
}
__device__ __forceinline__ float sqrt_approx(float v) {
    float r;
    asm("sqrt.approx.f32 %0, %1;" : "=f"(r) : "f"(v));
    return r;
}
__device__ __forceinline__ float ex2_approx(float v) {
    float r;
    asm("ex2.approx.f32 %0, %1;" : "=f"(r) : "f"(v));
    return r;
}
__device__ __forceinline__ void ldm_x4(uint32_t addr, uint32_t& r0, uint32_t& r1,
                                       uint32_t& r2, uint32_t& r3) {
    asm volatile("ldmatrix.sync.aligned.m8n8.x4.shared.b16 {%0,%1,%2,%3}, [%4];"
                 : "=r"(r0), "=r"(r1), "=r"(r2), "=r"(r3) : "r"(addr));
}
__device__ __forceinline__ void mma_tf32(float* d, const uint32_t* a,
                                         uint32_t b0, uint32_t b1) {
    asm volatile(
        "mma.sync.aligned.m16n8k8.row.col.f32.tf32.tf32.f32 "
        "{%0,%1,%2,%3}, {%4,%5,%6,%7}, {%8,%9}, {%0,%1,%2,%3};"
        : "+f"(d[0]), "+f"(d[1]), "+f"(d[2]), "+f"(d[3])
        : "r"(a[0]), "r"(a[1]), "r"(a[2]), "r"(a[3]), "r"(b0), "r"(b1));
}
__device__ __forceinline__ void cp16(uint32_t dst, const float* src) {
    asm volatile("cp.async.cg.shared.global [%0], [%1], 16;"
                 :: "r"(dst), "l"(src));
}
__device__ __forceinline__ void cp_commit() {
    asm volatile("cp.async.commit_group;");
}
__device__ __forceinline__ void cp_wait1() {
    asm volatile("cp.async.wait_group 1;");
}

// ---------------- prep: row norms of x and C ----------------
__global__ void prep_norms(const float* __restrict__ x,
                           const float* __restrict__ cbk, int N, int K) {
    int w    = (blockIdx.x * blockDim.x + threadIdx.x) >> 5;
    int lane = threadIdx.x & 31;
    if (w >= N + K) return;
    const float* src;
    float* dst;
    if (w < N) { src = x + (long long)w * DD;         dst = g_x2 + w; }
    else       { src = cbk + (long long)(w - N) * DD; dst = g_c2 + (w - N); }
    float s = 0.f;
    #pragma unroll
    for (int i = lane; i < DD / 4; i += 32) {
        float4 v = ((const float4*)src)[i];
        s += v.x * v.x + v.y * v.y + v.z * v.z + v.w * v.w;
    }
    #pragma unroll
    for (int d = 16; d > 0; d >>= 1) s += __shfl_xor_sync(0xffffffffu, s, d);
    if (lane == 0) *dst = s;
}

// ---------------- prep: convert codebook to tf32 bits ----------------
__global__ void prep_cvt(const float* __restrict__ cbk, int total4) {
    int i = blockIdx.x * blockDim.x + threadIdx.x;
    if (i >= total4) return;
    float4 v = ((const float4*)cbk)[i];
    uint4 u;
    u.x = cvt_rna_tf32(v.x); u.y = cvt_rna_tf32(v.y);
    u.z = cvt_rna_tf32(v.z); u.w = cvt_rna_tf32(v.w);
    ((uint4*)g_cbt)[i] = u;
}

// ---------------- main fused kernel ----------------
__global__ __launch_bounds__(THREADS, 1)
void vq_tc_kernel(const float* __restrict__ x,
                  float* __restrict__ out, int Ktot)
{
    extern __shared__ float sm[];
    float* xs = sm + OFF_XS;
    float* cs = sm + OFF_CS;   // 2 stages (pre-converted tf32 bits)
    float* ps = sm + OFF_PS;
    float* lb = sm + OFF_LB;   // 2 x 128 partial row sums

    const int tid  = threadIdx.x;
    const int w    = tid >> 5;      // 0..15
    const int lane = tid & 31;
    const int wr   = w & 7;         // MMA1 r-stripe: rows 16*wr..+15
    const int wj   = w >> 3;        // MMA1 j-half: j 16*wj..+15
    const int q    = lane >> 2;     // 0..7
    const int m    = lane & 3;      // 0..3
    const int lrow = lane & 15;
    const int lkof = (lane & 16) >> 2;
    const long long row0 = (long long)blockIdx.x * BM;

    const uint32_t xs_b = (uint32_t)__cvta_generic_to_shared(xs);
    const uint32_t cs_b = (uint32_t)__cvta_generic_to_shared(cs);
    const uint32_t ps_b = (uint32_t)__cvta_generic_to_shared(ps);

    // ---- stage x tile [128][256] (cvt.rna -> tf32 bits) ----
    for (int e = tid; e < BM * DD / 4; e += THREADS) {
        int r = e >> 6, c4 = e & 63;
        float4 v = ((const float4*)(x + (row0 + r) * DD))[c4];
        uint4 u;
        u.x = cvt_rna_tf32(v.x); u.y = cvt_rna_tf32(v.y);
        u.z = cvt_rna_tf32(v.z); u.w = cvt_rna_tf32(v.w);
        *(uint4*)(xs + r * XS_STRIDE + c4 * 4) = u;
    }

    // ---- per-lane r constants (warp r-stripe: 16*wr .. +15) ----
    float x2v[2][2], m2v[2][2];
    #pragma unroll
    for (int nf = 0; nf < 2; nf++)
        #pragma unroll
        for (int par = 0; par < 2; par++) {
            int r = 16 * wr + 8 * nf + 2 * m + par;
            float xx = g_x2[row0 + r];
            x2v[nf][par] = xx;
            m2v[nf][par] = LOG2E10 * sqrt_approx(xx);
        }

    // O^T accumulators: warp owns d-range 16*w..+15, all 128 r (16 nt)
    float o[16][4];
    #pragma unroll
    for (int nt = 0; nt < 16; nt++)
        #pragma unroll
        for (int c = 0; c < 4; c++) o[nt][c] = 0.f;
    float lsum[2][2] = {{0.f, 0.f}, {0.f, 0.f}};

    const int nTiles = Ktot / BN;

    // ---- prologue: issue C-tile stages 0 and 1 (from pre-converted g_cbt) ----
    #pragma unroll
    for (int s = 0; s < 2; s++) {
        const float* src0 = g_cbt + (long long)s * BN * DD;
        for (int e = tid; e < BN * DD / 4; e += THREADS) {
            int r = e >> 6, c4 = e & 63;
            cp16(cs_b + (s * CS_STAGE + r * CS_STRIDE + c4 * 4) * 4,
                 src0 + r * DD + c4 * 4);
        }
        cp_commit();
    }

    for (int kt = 0; kt < nTiles; kt++) {
        const int col0 = kt * BN;
        const int buf  = kt & 1;
        const float*  csb   = cs + buf * CS_STAGE;
        const uint32_t cs_bb = cs_b + buf * CS_STAGE * 4;

        // c2 for this lane's j positions (j = 16*wj + q + 8h)
        float c2v[2];
        c2v[0] = g_c2[col0 + 16 * wj + q];
        c2v[1] = g_c2[col0 + 16 * wj + q + 8];

        cp_wait1();          // stage kt landed
        __syncthreads();     // visible to all; ps reads of kt-1 done

        // ---- MMA1: S^T[16j x 16r per warp] = C * X^T ----
        float sfr[2][4];     // [nf][acc]
        #pragma unroll
        for (int nf = 0; nf < 2; nf++)
            #pragma unroll
            for (int c = 0; c < 4; c++) sfr[nf][c] = 0.f;

        #pragma unroll 8
        for (int kk = 0; kk < 32; kk++) {
            const int k0 = kk * 8;
            uint32_t a[4];
            {
                uint32_t ad = cs_bb +
                    ((16 * wj + lrow) * CS_STRIDE + k0 + lkof) * 4;
                ldm_x4(ad, a[0], a[1], a[2], a[3]);
            }
            uint32_t b0, b1, b2, b3;
            {
                uint32_t ad = xs_b +
                    ((16 * wr + lrow) * XS_STRIDE + k0 + lkof) * 4;
                ldm_x4(ad, b0, b1, b2, b3);
            }
            mma_tf32(sfr[0], a, b0, b2);
            mma_tf32(sfr[1], a, b1, b3);
        }

        // ---- epilogue: p = exp2(m2[r] - L*sqrt(x2[r]+c2[j]-2s)) ----
        #pragma unroll
        for (int nf = 0; nf < 2; nf++) {
            float s0 = sfr[nf][0];   // (j0+q,   rA)
            float s1 = sfr[nf][1];   // (j0+q,   rA+1)
            float s2 = sfr[nf][2];   // (j0+q+8, rA)
            float s3 = sfr[nf][3];   // (j0+q+8, rA+1)
            float sq0 = fmaf(-2.f, s0, x2v[nf][0]) + c2v[0];
            float sq1 = fmaf(-2.f, s1, x2v[nf][1]) + c2v[0];
            float sq2 = fmaf(-2.f, s2, x2v[nf][0]) + c2v[1];
            float sq3 = fmaf(-2.f, s3, x2v[nf][1]) + c2v[1];
            float r0 = sqrt_approx(fmaxf(sq0, 0.f));
            float r1 = sqrt_approx(fmaxf(sq1, 0.f));
            float r2 = sqrt_approx(fmaxf(sq2, 0.f));
            float r3 = sqrt_approx(fmaxf(sq3, 0.f));
            float p0 = ex2_approx(fmaf(-LOG2E10, r0, m2v[nf][0]));
            float p1 = ex2_approx(fmaf(-LOG2E10, r1, m2v[nf][1]));
            float p2 = ex2_approx(fmaf(-LOG2E10, r2, m2v[nf][0]));
            float p3 = ex2_approx(fmaf(-LOG2E10, r3, m2v[nf][1]));
            lsum[nf][0] += p0 + p2;
            lsum[nf][1] += p1 + p3;
            sfr[nf][0] = __uint_as_float(cvt_rna_tf32(p0));
            sfr[nf][1] = __uint_as_float(cvt_rna_tf32(p1));
            sfr[nf][2] = __uint_as_float(cvt_rna_tf32(p2));
            sfr[nf][3] = __uint_as_float(cvt_rna_tf32(p3));
        }

        // ---- store P (row-major [r][j]) — conflict-free scatter ----
        {
            const int jl = 16 * wj + q;
            #pragma unroll
            for (int nf = 0; nf < 2; nf++) {
                int rA = 16 * wr + 8 * nf + 2 * m;
                ps[rA * PS_STRIDE + jl]           = sfr[nf][0];
                ps[(rA + 1) * PS_STRIDE + jl]     = sfr[nf][1];
                ps[rA * PS_STRIDE + jl + 8]       = sfr[nf][2];
                ps[(rA + 1) * PS_STRIDE + jl + 8] = sfr[nf][3];
            }
        }
        __syncthreads();

        // ---- MMA2: O^T += C^T * P^T  (warp owns 16 d = 16*w..+15) ----
        #pragma unroll
        for (int jk = 0; jk < 4; jk++) {
            const int jg = 8 * jk;
            uint32_t a2[4];
            {
                const float* cp0 = csb + (jg + m) * CS_STRIDE + 16 * w;
                const float* cp1 = csb + (jg + 4 + m) * CS_STRIDE + 16 * w;
                a2[0] = __float_as_uint(cp0[q]);
                a2[1] = __float_as_uint(cp0[q + 8]);
                a2[2] = __float_as_uint(cp1[q]);
                a2[3] = __float_as_uint(cp1[q + 8]);
            }
            uint32_t bb[16][2];
            #pragma unroll
            for (int g = 0; g < 8; g++) {
                uint32_t r0, r1, r2, r3;
                uint32_t ad = ps_b +
                    ((16 * g + lrow) * PS_STRIDE + jg + lkof) * 4;
                ldm_x4(ad, r0, r1, r2, r3);
                bb[2 * g][0] = r0;     bb[2 * g][1] = r2;
                bb[2 * g + 1][0] = r1; bb[2 * g + 1][1] = r3;
            }
            #pragma unroll
            for (int nt = 0; nt < 16; nt++)
                mma_tf32(o[nt], a2, bb[nt][0], bb[nt][1]);
        }
        __syncthreads();   // stage `buf` + ps fully consumed

        // ---- issue C-tile kt+2 into the freed stage ----
        if (kt + 2 < nTiles) {
            const float* src0 = g_cbt + (long long)(col0 + 2 * BN) * DD;
            for (int e = tid; e < BN * DD / 4; e += THREADS) {
                int r = e >> 6, c4 = e & 63;
                cp16(cs_b + (buf * CS_STAGE + r * CS_STRIDE + c4 * 4) * 4,
                     src0 + r * DD + c4 * 4);
            }
        }
        cp_commit();   // keep group counting aligned even on tail tiles
    }

    // ---- reduce lsum over q-lanes (j direction), publish lb[wj][r] ----
    #pragma unroll
    for (int nf = 0; nf < 2; nf++)
        #pragma unroll
        for (int par = 0; par < 2; par++) {
            float v = lsum[nf][par];
            v += __shfl_xor_sync(0xffffffffu, v, 4);
            v += __shfl_xor_sync(0xffffffffu, v, 8);
            v += __shfl_xor_sync(0xffffffffu, v, 16);
            if (q == 0)
                lb[wj * BM + 16 * wr + 8 * nf + 2 * m + par] = v;
        }
    __syncthreads();

    // ---- finalize: out[r][d] = O^T[d][r] / l[r] ----
    #pragma unroll
    for (int nt = 0; nt < 16; nt++) {
        int rA = 8 * nt + 2 * m;
        float invA = 1.f / (lb[rA] + lb[BM + rA]);
        float invB = 1.f / (lb[rA + 1] + lb[BM + rA + 1]);
        int d0 = 16 * w;
        float* oA = out + (row0 + rA) * DD + d0;
        float* oB = out + (row0 + rA + 1) * DD + d0;
        oA[q]     = o[nt][0] * invA;
        oB[q]     = o[nt][1] * invB;
        oA[q + 8] = o[nt][2] * invA;
        oB[q + 8] = o[nt][3] * invB;
    }
}

// Fill possible tail of d_out (the reference's second tuple element, -1)
__global__ void fill_tail_kernel(float* p, long long n)
{
    long long i = (long long)blockIdx.x * blockDim.x + threadIdx.x;
    if (i < n) p[i] = -1.0f;
}

extern "C" void kernel_launch(void* const* d_in, const int* in_sizes, int n_in,
                              void* d_out, int out_size)
{
    const float* x   = (const float*)d_in[0];
    const float* cbk = (const float*)d_in[1];
    float* out = (float*)d_out;

    const int N = in_sizes[0] / DD;   // 32768
    const int K = in_sizes[1] / DD;   // 8192

    // prep: row norms + codebook tf32 conversion
    {
        int warps = N + K;
        int thr = 256;
        int blocks = (warps * 32 + thr - 1) / thr;
        prep_norms<<<blocks, thr>>>(x, cbk, N, K);

        int total4 = K * DD / 4;
        prep_cvt<<<(total4 + 255) / 256, 256>>>(cbk, total4);
    }

    cudaFuncSetAttribute(vq_tc_kernel,
                         cudaFuncAttributeMaxDynamicSharedMemorySize, SMEM_BYTES);
    vq_tc_kernel<<<N / BM, THREADS, SMEM_BYTES>>>(x, out, K);

    long long nd = (long long)N * DD;
    if ((long long)out_size > nd) {
        long long tail = (long long)out_size - nd;
        int thr = 256;
        int blocks = (int)((tail + thr - 1) / thr);
        fill_tail_kernel<<<blocks, thr>>>(out + nd, tail);
    }
}

// round 17
// speedup vs baseline: 2.0335x; 2.0335x over previous
#include <cuda_runtime.h>
#include <cuda_fp16.h>
#include <cstdint>

// Fused soft-VQ, fp16 mma.sync m16n8k16 (10-bit mantissa = tf32 accuracy,
// half the mma/ldmatrix/smem traffic), transposed operands:
//   MMA1: S^T[64j x 128r] = C * X^T   (warp grid 2j x 4r)
//   MMA2: O^T[256d x 128r] = C^T * P^T (warp owns 32d; B-frags: natural ldmatrix on P)
// out = softmax(-10 * ||x - C||) @ C ; N=32768, K=8192, D=256

#define DD  256
#define BM  128
#define BN  64
#define THREADS 256
#define XSH 264          // half stride: 528 B, mod 128 = 16 -> ldmatrix conflict-free
#define CSH 264
#define PSH 72           // 144 B, mod 128 = 16
#define XSB (XSH * 2)
#define CSB (CSH * 2)
#define PSB (PSH * 2)

#define NMAX 32768
#define KMAX 8192

// smem byte offsets
#define OFF_XS 0                         // 128 x 264 half = 67584 B
#define OFF_CS 67584                     // 64 x 264 half  = 33792 B
#define OFF_PS 101376                    // 128 x 72 half  = 18432 B
#define OFF_LB 119808                    // 2 x 128 float  = 1024 B
#define SMEM_BYTES 120832

#define LOG2E10 14.4269504088896f   // 10 * log2(e)

__device__ float g_x2[NMAX];
__device__ float g_c2[KMAX];

// ---------------- helpers ----------------
__device__ __forceinline__ uint32_t f2h2(float lo, float hi) {
    __half2 h = __floats2half2_rn(lo, hi);
    return *reinterpret_cast<uint32_t*>(&h);
}
__device__ __forceinline__ float sqrt_approx(float v) {
    float r; asm("sqrt.approx.f32 %0, %1;" : "=f"(r) : "f"(v)); return r;
}
__device__ __forceinline__ float ex2_approx(float v) {
    float r; asm("ex2.approx.f32 %0, %1;" : "=f"(r) : "f"(v)); return r;
}
__device__ __forceinline__ void ldm_x4(uint32_t addr, uint32_t& r0, uint32_t& r1,
                                       uint32_t& r2, uint32_t& r3) {
    asm volatile("ldmatrix.sync.aligned.m8n8.x4.shared.b16 {%0,%1,%2,%3}, [%4];"
                 : "=r"(r0), "=r"(r1), "=r"(r2), "=r"(r3) : "r"(addr));
}
__device__ __forceinline__ void mma_f16(float* d, const uint32_t* a,
                                        uint32_t b0, uint32_t b1) {
    asm volatile(
        "mma.sync.aligned.m16n8k16.row.col.f32.f16.f16.f32 "
        "{%0,%1,%2,%3}, {%4,%5,%6,%7}, {%8,%9}, {%0,%1,%2,%3};"
        : "+f"(d[0]), "+f"(d[1]), "+f"(d[2]), "+f"(d[3])
        : "r"(a[0]), "r"(a[1]), "r"(a[2]), "r"(a[3]), "r"(b0), "r"(b1));
}

// ---------------- prep: row norms of x and C ----------------
__global__ void prep_norms(const float* __restrict__ x,
                           const float* __restrict__ cbk, int N, int K) {
    int w    = (blockIdx.x * blockDim.x + threadIdx.x) >> 5;
    int lane = threadIdx.x & 31;
    if (w >= N + K) return;
    const float* src;
    float* dst;
    if (w < N) { src = x + (long long)w * DD;         dst = g_x2 + w; }
    else       { src = cbk + (long long)(w - N) * DD; dst = g_c2 + (w - N); }
    float s = 0.f;
    #pragma unroll
    for (int i = lane; i < DD / 4; i += 32) {
        float4 v = ((const float4*)src)[i];
        s += v.x * v.x + v.y * v.y + v.z * v.z + v.w * v.w;
    }
    #pragma unroll
    for (int d = 16; d > 0; d >>= 1) s += __shfl_xor_sync(0xffffffffu, s, d);
    if (lane == 0) *dst = s;
}

// ---------------- main fused kernel ----------------
__global__ __launch_bounds__(THREADS, 1)
void vq_fp16_kernel(const float* __restrict__ x,
                    const float* __restrict__ cbk,
                    float* __restrict__ out, int Ktot)
{
    extern __shared__ char smem[];
    __half* xs = (__half*)(smem + OFF_XS);
    __half* cs = (__half*)(smem + OFF_CS);
    __half* ps = (__half*)(smem + OFF_PS);
    float*  lb = (float*)(smem + OFF_LB);
    const unsigned short* csu = (const unsigned short*)cs;

    const int tid  = threadIdx.x;
    const int w    = tid >> 5;
    const int lane = tid & 31;
    const int wm   = w >> 2;       // 0..1 : S^T j-half  (32 j per warp)
    const int wn   = w & 3;        // 0..3 : S^T r-quarter (32 r per warp)
    const int q    = lane >> 2;    // 0..7
    const int m    = lane & 3;     // 0..3
    const int lrow = lane & 15;
    const int lk16 = (lane & 16);  // +16 bytes (k+8 halves) for upper 16 lanes
    const long long row0 = (long long)blockIdx.x * BM;

    const uint32_t xs_b = (uint32_t)__cvta_generic_to_shared(xs);
    const uint32_t cs_b = (uint32_t)__cvta_generic_to_shared(cs);
    const uint32_t ps_b = (uint32_t)__cvta_generic_to_shared(ps);

    // ---- stage x tile [128][256] (fp32 -> half2) ----
    for (int e = tid; e < BM * DD / 4; e += THREADS) {
        int r = e >> 6, c4 = e & 63;
        float4 v = ((const float4*)(x + (row0 + r) * DD))[c4];
        uint32_t h0 = f2h2(v.x, v.y), h1 = f2h2(v.z, v.w);
        asm volatile("st.shared.v2.b32 [%0], {%1, %2};"
                     :: "r"(xs_b + r * XSB + c4 * 8), "r"(h0), "r"(h1));
    }

    // ---- per-lane r constants (warp r-range: 32*wn .. +31) ----
    float x2v[4][2], m2v[4][2];
    #pragma unroll
    for (int nf = 0; nf < 4; nf++)
        #pragma unroll
        for (int par = 0; par < 2; par++) {
            int r = 32 * wn + 8 * nf + 2 * m + par;
            float xx = g_x2[row0 + r];
            x2v[nf][par] = xx;
            m2v[nf][par] = LOG2E10 * sqrt_approx(xx);
        }

    // O^T accumulators: warp owns d-range 32*w..+31 (2 mtd), all 128 r (16 nt)
    float o[2][16][4];
    #pragma unroll
    for (int mtd = 0; mtd < 2; mtd++)
        #pragma unroll
        for (int nt = 0; nt < 16; nt++)
            #pragma unroll
            for (int c = 0; c < 4; c++) o[mtd][nt][c] = 0.f;
    float lsum[4][2] = {{0.f,0.f},{0.f,0.f},{0.f,0.f},{0.f,0.f}};

    const int nTiles = Ktot / BN;
    for (int kt = 0; kt < nTiles; kt++) {
        const int col0 = kt * BN;

        // ---- stage C tile [64][256] (fp32 -> half2) ----
        for (int e = tid; e < BN * DD / 4; e += THREADS) {
            int r = e >> 6, c4 = e & 63;
            float4 v = ((const float4*)(cbk + (long long)(col0 + r) * DD))[c4];
            uint32_t h0 = f2h2(v.x, v.y), h1 = f2h2(v.z, v.w);
            asm volatile("st.shared.v2.b32 [%0], {%1, %2};"
                         :: "r"(cs_b + r * CSB + c4 * 8), "r"(h0), "r"(h1));
        }

        // c2 for this lane's j positions (j = 32wm + 16mt + q + 8h)
        float c2v[2][2];
        #pragma unroll
        for (int mt = 0; mt < 2; mt++)
            #pragma unroll
            for (int h = 0; h < 2; h++)
                c2v[mt][h] = g_c2[col0 + 32 * wm + 16 * mt + q + 8 * h];

        __syncthreads();   // cs staged (also orders xs on iter 0)

        // ---- MMA1: S^T[32j x 32r] = C * X^T  (16 K-chunks of 16) ----
        float sfr[2][4][4];
        #pragma unroll
        for (int mt = 0; mt < 2; mt++)
            #pragma unroll
            for (int nf = 0; nf < 4; nf++)
                #pragma unroll
                for (int c = 0; c < 4; c++) sfr[mt][nf][c] = 0.f;

        #pragma unroll 8
        for (int kk = 0; kk < 16; kk++) {
            const int k0 = kk * 16;
            uint32_t a[2][4];
            #pragma unroll
            for (int mt = 0; mt < 2; mt++) {
                uint32_t ad = cs_b + (32 * wm + 16 * mt + lrow) * CSB + k0 * 2 + lk16;
                ldm_x4(ad, a[mt][0], a[mt][1], a[mt][2], a[mt][3]);
            }
            uint32_t bfr[4][2];
            #pragma unroll
            for (int bp = 0; bp < 2; bp++) {
                uint32_t r0, r1, r2, r3;
                uint32_t ad = xs_b + (32 * wn + 16 * bp + lrow) * XSB + k0 * 2 + lk16;
                ldm_x4(ad, r0, r1, r2, r3);
                bfr[2 * bp][0] = r0;     bfr[2 * bp][1] = r2;
                bfr[2 * bp + 1][0] = r1; bfr[2 * bp + 1][1] = r3;
            }
            #pragma unroll
            for (int mt = 0; mt < 2; mt++)
                #pragma unroll
                for (int nf = 0; nf < 4; nf++)
                    mma_f16(sfr[mt][nf], a[mt], bfr[nf][0], bfr[nf][1]);
        }

        // ---- epilogue: p = exp2(m2[r] - L*sqrt(x2[r]+c2[j]-2s)) ; P -> half ----
        #pragma unroll
        for (int mt = 0; mt < 2; mt++)
            #pragma unroll
            for (int nf = 0; nf < 4; nf++) {
                float s0 = sfr[mt][nf][0];   // (j0+q,   rA)
                float s1 = sfr[mt][nf][1];   // (j0+q,   rA+1)
                float s2 = sfr[mt][nf][2];   // (j0+q+8, rA)
                float s3 = sfr[mt][nf][3];   // (j0+q+8, rA+1)
                float sq0 = fmaf(-2.f, s0, x2v[nf][0]) + c2v[mt][0];
                float sq1 = fmaf(-2.f, s1, x2v[nf][1]) + c2v[mt][0];
                float sq2 = fmaf(-2.f, s2, x2v[nf][0]) + c2v[mt][1];
                float sq3 = fmaf(-2.f, s3, x2v[nf][1]) + c2v[mt][1];
                float r0 = sqrt_approx(fmaxf(sq0, 0.f));
                float r1 = sqrt_approx(fmaxf(sq1, 0.f));
                float r2 = sqrt_approx(fmaxf(sq2, 0.f));
                float r3 = sqrt_approx(fmaxf(sq3, 0.f));
                float p0 = ex2_approx(fmaf(-LOG2E10, r0, m2v[nf][0]));
                float p1 = ex2_approx(fmaf(-LOG2E10, r1, m2v[nf][1]));
                float p2 = ex2_approx(fmaf(-LOG2E10, r2, m2v[nf][0]));
                float p3 = ex2_approx(fmaf(-LOG2E10, r3, m2v[nf][1]));
                lsum[nf][0] += p0 + p2;
                lsum[nf][1] += p1 + p3;
                // store P as half: row r, col j (full 64-wide buffer)
                int jl = 32 * wm + 16 * mt + q;
                int rA = 32 * wn + 8 * nf + 2 * m;
                ps[rA * PSH + jl]           = __float2half_rn(p0);
                ps[(rA + 1) * PSH + jl]     = __float2half_rn(p1);
                ps[rA * PSH + jl + 8]       = __float2half_rn(p2);
                ps[(rA + 1) * PSH + jl + 8] = __float2half_rn(p3);
            }
        __syncthreads();

        // ---- MMA2: O^T += C^T * P^T  (4 j-chunks of 16) ----
        #pragma unroll
        for (int jk = 0; jk < 4; jk++) {
            const int jg = 16 * jk;
            uint32_t a2[2][4];
            #pragma unroll
            for (int mtd = 0; mtd < 2; mtd++) {
                const int d0 = 32 * w + 16 * mtd;
                uint32_t lo, hi;
                // a0: (d0+q, j=jg+2m, jg+2m+1)
                lo = csu[(jg + 2 * m) * CSH + d0 + q];
                hi = csu[(jg + 2 * m + 1) * CSH + d0 + q];
                a2[mtd][0] = lo | (hi << 16);
                // a1: (d0+q+8, j=jg+2m, +1)
                lo = csu[(jg + 2 * m) * CSH + d0 + q + 8];
                hi = csu[(jg + 2 * m + 1) * CSH + d0 + q + 8];
                a2[mtd][1] = lo | (hi << 16);
                // a2: (d0+q, j=jg+8+2m, +1)
                lo = csu[(jg + 8 + 2 * m) * CSH + d0 + q];
                hi = csu[(jg + 8 + 2 * m + 1) * CSH + d0 + q];
                a2[mtd][2] = lo | (hi << 16);
                // a3: (d0+q+8, j=jg+8+2m, +1)
                lo = csu[(jg + 8 + 2 * m) * CSH + d0 + q + 8];
                hi = csu[(jg + 8 + 2 * m + 1) * CSH + d0 + q + 8];
                a2[mtd][3] = lo | (hi << 16);
            }
            uint32_t bb[16][2];
            #pragma unroll
            for (int g = 0; g < 8; g++) {
                uint32_t r0, r1, r2, r3;
                uint32_t ad = ps_b + (16 * g + lrow) * PSB + jg * 2 + lk16;
                ldm_x4(ad, r0, r1, r2, r3);
                bb[2 * g][0] = r0;     bb[2 * g][1] = r2;
                bb[2 * g + 1][0] = r1; bb[2 * g + 1][1] = r3;
            }
            #pragma unroll
            for (int mtd = 0; mtd < 2; mtd++)
                #pragma unroll
                for (int nt = 0; nt < 16; nt++)
                    mma_f16(o[mtd][nt], a2[mtd], bb[nt][0], bb[nt][1]);
        }
        __syncthreads();   // cs + ps fully consumed before next restage
    }

    // ---- reduce lsum over q-lanes (j direction), publish per (wm, r) ----
    #pragma unroll
    for (int nf = 0; nf < 4; nf++)
        #pragma unroll
        for (int par = 0; par < 2; par++) {
            float v = lsum[nf][par];
            v += __shfl_xor_sync(0xffffffffu, v, 4);
            v += __shfl_xor_sync(0xffffffffu, v, 8);
            v += __shfl_xor_sync(0xffffffffu, v, 16);
            if (q == 0)
                lb[wm * BM + 32 * wn + 8 * nf + 2 * m + par] = v;
        }
    __syncthreads();

    // ---- finalize: out[r][d] = O^T[d][r] / l[r] ----
    #pragma unroll
    for (int nt = 0; nt < 16; nt++) {
        int rA = 8 * nt + 2 * m;
        float invA = 1.f / (lb[rA] + lb[BM + rA]);
        float invB = 1.f / (lb[rA + 1] + lb[BM + rA + 1]);
        #pragma unroll
        for (int mtd = 0; mtd < 2; mtd++) {
            int d0 = 32 * w + 16 * mtd;
            float* oA = out + (row0 + rA) * DD + d0;
            float* oB = out + (row0 + rA + 1) * DD + d0;
            oA[q]     = o[mtd][nt][0] * invA;
            oB[q]     = o[mtd][nt][1] * invB;
            oA[q + 8] = o[mtd][nt][2] * invA;
            oB[q + 8] = o[mtd][nt][3] * invB;
        }
    }
}

// Fill possible tail of d_out (the reference's second tuple element, -1)
__global__ void fill_tail_kernel(float* p, long long n)
{
    long long i = (long long)blockIdx.x * blockDim.x + threadIdx.x;
    if (i < n) p[i] = -1.0f;
}

extern "C" void kernel_launch(void* const* d_in, const int* in_sizes, int n_in,
                              void* d_out, int out_size)
{
    const float* x   = (const float*)d_in[0];
    const float* cbk = (const float*)d_in[1];
    float* out = (float*)d_out;

    const int N = in_sizes[0] / DD;   // 32768
    const int K = in_sizes[1] / DD;   // 8192

    // prep: row norms
    {
        int warps = N + K;
        int thr = 256;
        int blocks = (warps * 32 + thr - 1) / thr;
        prep_norms<<<blocks, thr>>>(x, cbk, N, K);
    }

    cudaFuncSetAttribute(vq_fp16_kernel,
                         cudaFuncAttributeMaxDynamicSharedMemorySize, SMEM_BYTES);
    vq_fp16_kernel<<<N / BM, THREADS, SMEM_BYTES>>>(x, cbk, out, K);

    long long nd = (long long)N * DD;
    if ((long long)out_size > nd) {
        long long tail = (long long)out_size - nd;
        int thr = 256;
        int blocks = (int)((tail + thr - 1) / thr);
        fill_tail_kernel<<<blocks, thr>>>(out + nd, tail);
    }
}